// round 17
// baseline (speedup 1.0000x reference)
#include <cuda_runtime.h>
#include <cuda_fp16.h>
#include <cstdint>

#define BB 256
#define PP 196
#define DD 512
#define AA 512
#define MM (BB*PP)   // 50176

// ---------------- scratch (__device__ globals; no allocs) -------------------
__device__ float g_hidden[BB*AA];      // hidden + bv
__device__ float g_sh[BB*AA];          // st@Ws + bs + hidden (pre-tanh)
__device__ float g_z[BB*PP];           // logits
// Wv^T fp16 plane, fragment-packed: [n(512)][chunk c(32)][slot t(4)] uint2
// slot t of chunk c = { f16pair(k=16c+2t), f16pair(k=16c+2t+8) }
__device__ uint4 g_WvH4[512*64];       // 512KB

// ---------------- helpers ---------------------------------------------------
__device__ __forceinline__ float tanhapx(float x) {
    float y; asm("tanh.approx.f32 %0, %1;" : "=f"(y) : "f"(x)); return y;
}
__device__ __forceinline__ uint32_t pack2h(float a, float b) {
    const __half ha = __float2half(a), hb = __float2half(b);
    return (uint32_t)__half_as_ushort(ha) |
           ((uint32_t)__half_as_ushort(hb) << 16);
}
__device__ __forceinline__ void mma16h(float* c, const uint32_t* a, const uint32_t* b) {
    asm volatile(
        "mma.sync.aligned.m16n8k16.row.col.f32.f16.f16.f32 "
        "{%0,%1,%2,%3}, {%4,%5,%6,%7}, {%8,%9}, {%0,%1,%2,%3};"
        : "+f"(c[0]), "+f"(c[1]), "+f"(c[2]), "+f"(c[3])
        : "r"(a[0]), "r"(a[1]), "r"(a[2]), "r"(a[3]), "r"(b[0]), "r"(b[1]));
}
__device__ __forceinline__ void cpasync16(uint32_t dst, const void* src) {
    asm volatile("cp.async.ca.shared.global [%0], [%1], 16;" :: "r"(dst), "l"(src));
}
#define CP_COMMIT() asm volatile("cp.async.commit_group;" ::: "memory")
#define CP_WAIT0()  asm volatile("cp.async.wait_group 0;" ::: "memory")

// ---------------------------------------------------------------------------
// K1 fused: blocks 0..127 -> prep (hidden/g_sh GEMMs); 128..143 -> conv_wv.
// prep thread = 1 batch x 4 a-cols: per k only 2x LDS.128 + 2 broadcasts.
// ---------------------------------------------------------------------------
__global__ void __launch_bounds__(256) k_prepc(
    const float* __restrict__ dh, const float* __restrict__ st,
    const float* __restrict__ Wh, const float* __restrict__ bh,
    const float* __restrict__ Ws, const float* __restrict__ bs,
    const float* __restrict__ bv, const float* __restrict__ Wv)
{
    __shared__ float dh_s[8][33], st_s[8][33];
    __shared__ float Wh_s[32][128], Ws_s[32][128];
    __shared__ float cv_s[32][65];
    const int tid = threadIdx.x;

    if (blockIdx.x >= 128) {
        // ---- conv_wv: Wv[k][n] fp32 -> packed fp16 plane [n][k] ----
        const int n0 = (blockIdx.x - 128) * 32;
        uint2* WvH2 = (uint2*)g_WvH4;
        for (int k0 = 0; k0 < DD; k0 += 64) {
            __syncthreads();
            #pragma unroll
            for (int j = 0; j < 8; ++j) {
                const int idx = tid + j*256;
                const int k = idx >> 5, n = idx & 31;
                cv_s[n][k] = Wv[(size_t)(k0 + k)*AA + n0 + n];
            }
            __syncthreads();
            #pragma unroll
            for (int j = 0; j < 2; ++j) {
                const int i = tid + j*256;           // 32n x 16 slots
                const int n = i >> 4, q = i & 15;
                const int c = q >> 2, t = q & 3;
                const int kl = c*16 + 2*t;
                uint2 w;
                w.x = pack2h(cv_s[n][kl],   cv_s[n][kl+1]);
                w.y = pack2h(cv_s[n][kl+8], cv_s[n][kl+9]);
                WvH2[(size_t)(n0 + n)*128 + (k0/16 + c)*4 + t] = w;
            }
        }
        return;
    }

    // ---- prep: tile 8b x 128a; BK=32; thread = 1b x 4a ----
    const int b0  = (blockIdx.x >> 2) * 8;
    const int a0  = (blockIdx.x & 3) * 128;
    const int ag  = tid & 31;            // a-quad index (a = a0 + ag*4 .. +3)
    const int bb  = tid >> 5;            // batch 0..7 (one per warp)

    float acch[4] = {}, accs[4] = {};

    float4 pwh[4], pws[4];
    float  pdh, pst;
    const int wkk = tid >> 5, wnq = tid & 31;   // W staging slot (+j*8 rows)

    // prefetch stage 0
    #pragma unroll
    for (int j = 0; j < 4; ++j) {
        pwh[j] = *(const float4*)&Wh[(size_t)(wkk + j*8)*AA + a0 + wnq*4];
        pws[j] = *(const float4*)&Ws[(size_t)(wkk + j*8)*AA + a0 + wnq*4];
    }
    pdh = dh[(b0 + wkk)*DD + wnq];
    pst = st[(b0 + wkk)*DD + wnq];

    for (int kb = 0; kb < DD; kb += 32) {
        __syncthreads();
        dh_s[wkk][wnq] = pdh;
        st_s[wkk][wnq] = pst;
        #pragma unroll
        for (int j = 0; j < 4; ++j) {
            *(float4*)&Wh_s[wkk + j*8][wnq*4] = pwh[j];
            *(float4*)&Ws_s[wkk + j*8][wnq*4] = pws[j];
        }
        __syncthreads();
        if (kb + 32 < DD) {
            #pragma unroll
            for (int j = 0; j < 4; ++j) {
                pwh[j] = *(const float4*)&Wh[(size_t)(kb + 32 + wkk + j*8)*AA + a0 + wnq*4];
                pws[j] = *(const float4*)&Ws[(size_t)(kb + 32 + wkk + j*8)*AA + a0 + wnq*4];
            }
            pdh = dh[(b0 + wkk)*DD + kb + 32 + wnq];
            pst = st[(b0 + wkk)*DD + kb + 32 + wnq];
        }
        #pragma unroll 8
        for (int k = 0; k < 32; ++k) {
            const float4 wh4 = *(const float4*)&Wh_s[k][ag*4];
            const float4 ws4 = *(const float4*)&Ws_s[k][ag*4];
            const float dv = dh_s[bb][k], sv = st_s[bb][k];
            acch[0] += dv*wh4.x; acch[1] += dv*wh4.y;
            acch[2] += dv*wh4.z; acch[3] += dv*wh4.w;
            accs[0] += sv*ws4.x; accs[1] += sv*ws4.y;
            accs[2] += sv*ws4.z; accs[3] += sv*ws4.w;
        }
    }
    {
        const int b = b0 + bb, a = a0 + ag*4;
        const float4 bh4 = *(const float4*)&bh[a];
        const float4 bv4 = *(const float4*)&bv[a];
        const float4 bs4 = *(const float4*)&bs[a];
        float4 hv, sv;
        hv.x = acch[0] + bh4.x; hv.y = acch[1] + bh4.y;
        hv.z = acch[2] + bh4.z; hv.w = acch[3] + bh4.w;
        sv.x = accs[0] + bs4.x + hv.x; sv.y = accs[1] + bs4.y + hv.y;
        sv.z = accs[2] + bs4.z + hv.z; sv.w = accs[3] + bs4.w + hv.w;
        float4 ho;
        ho.x = hv.x + bv4.x; ho.y = hv.y + bv4.y;
        ho.z = hv.z + bv4.z; ho.w = hv.w + bv4.w;
        *(float4*)&g_hidden[(size_t)b*AA + a] = ho;
        *(float4*)&g_sh[(size_t)b*AA + a]     = sv;
    }
}

// ---------------------------------------------------------------------------
// K2: z[m] = bav + sum_a Wav[a]*tanh( enc[m,:]@Wv[:,a] + hidden[b(m),a] )
// fp16 m16n8k16 single pass. BM=128, BN=256 (nt=2), BK=64 (8 stages/nt);
// 512 thr / 16 warps (4m x 4n), warp 32x64. Double-buffered smem + cp.async.
// (UNCHANGED — frozen at the HMMA throughput floor.)
// ---------------------------------------------------------------------------
#define ASTR 20              // uint2 per A row (16 used + 4 pad)
#define BSTR 20              // uint2 per B row (16 used + 4 pad)
#define BUFSZ   61440
#define OFF_H0  122880
#define OFF_H1  123904
#define OFF_WAV 124928
#define OFF_ZS  125952
#define K2_SMEM 126464

__global__ void __launch_bounds__(512, 1) k_zgemm(
    const float* __restrict__ enc, const float* __restrict__ Wav,
    const float* __restrict__ bav)
{
    extern __shared__ unsigned char sm[];
    float* h0s  = (float*)(sm + OFF_H0);
    float* h1s  = (float*)(sm + OFF_H1);
    float* wavs = (float*)(sm + OFF_WAV);
    float* zs   = (float*)(sm + OFF_ZS);
    const uint32_t sbase = (uint32_t)__cvta_generic_to_shared(sm);

    const int tid  = threadIdx.x, lane = tid & 31, wid = tid >> 5;
    const int wm   = wid & 3;
    const int wn   = wid >> 2;
    const int gid  = lane >> 2, tig = lane & 3;
    const int m0   = blockIdx.x * 128;
    const int b0   = m0 / PP;
    const int b1   = (m0 + 127) / PP;
    const int bsplit = (b0 + 1) * PP;

    int sr_[4], sq_[4], skl_[4];
    #pragma unroll
    for (int j = 0; j < 4; ++j) {
        const int slot = tid + j*512;
        sr_[j]  = slot >> 4;
        sq_[j]  = slot & 15;
        skl_[j] = ((sq_[j] >> 2) << 4) + ((sq_[j] & 3) << 1);
    }
    int bn_[4], bs8_[4];
    #pragma unroll
    for (int j = 0; j < 4; ++j) {
        const int i = tid + j*512;
        bn_[j]  = i >> 3;
        bs8_[j] = i & 7;
    }

    if (tid < 128) zs[tid] = 0.f;

    for (int nt = 0; nt < 2; ++nt) {
        const int n0 = nt * 256;
        __syncthreads();
        for (int i = tid; i < 256; i += 512) {
            wavs[i] = Wav[n0 + i];
            h0s[i]  = g_hidden[(size_t)b0*AA + n0 + i];
            h1s[i]  = g_hidden[(size_t)b1*AA + n0 + i];
        }

        float acc[2][8][4];
        #pragma unroll
        for (int mi = 0; mi < 2; ++mi)
            #pragma unroll
            for (int ni = 0; ni < 8; ++ni)
                #pragma unroll
                for (int q = 0; q < 4; ++q) acc[mi][ni][q] = 0.f;

        {
            #pragma unroll
            for (int j = 0; j < 4; ++j) {
                const uint32_t dst = sbase + 20480u + bn_[j]*160u + bs8_[j]*16u;
                cpasync16(dst, &g_WvH4[(size_t)(n0 + bn_[j])*64 + bs8_[j]]);
            }
            CP_COMMIT();
            float2 pa[4][2];
            #pragma unroll
            for (int j = 0; j < 4; ++j) {
                const float* base = &enc[(size_t)(m0 + sr_[j])*DD + skl_[j]];
                pa[j][0] = *(const float2*)(base);
                pa[j][1] = *(const float2*)(base + 8);
            }
            uint2* Ah = (uint2*)(sm);
            #pragma unroll
            for (int j = 0; j < 4; ++j) {
                const int u = sr_[j]*ASTR + sq_[j];
                Ah[u] = make_uint2(pack2h(pa[j][0].x, pa[j][0].y),
                                   pack2h(pa[j][1].x, pa[j][1].y));
            }
            CP_WAIT0();
        }
        __syncthreads();

        int cur = 0;
        for (int kb = 0; kb < DD; kb += 64) {
            const int has_next = (kb + 64 < DD);
            const int nxt = cur ^ 1;
            float2 pa[4][2];
            if (has_next) {
                const int kc = ((kb + 64) >> 4) * 2;
                #pragma unroll
                for (int j = 0; j < 4; ++j) {
                    const uint32_t dst = sbase + (uint32_t)nxt*BUFSZ +
                        20480u + bn_[j]*160u + bs8_[j]*16u;
                    cpasync16(dst, &g_WvH4[(size_t)(n0 + bn_[j])*64 + kc + bs8_[j]]);
                }
                CP_COMMIT();
                #pragma unroll
                for (int j = 0; j < 4; ++j) {
                    const float* base =
                        &enc[(size_t)(m0 + sr_[j])*DD + kb + 64 + skl_[j]];
                    pa[j][0] = *(const float2*)(base);
                    pa[j][1] = *(const float2*)(base + 8);
                }
            }

            {
                uint2* Ah = (uint2*)(sm + cur*BUFSZ);
                uint2* Bh = (uint2*)(sm + cur*BUFSZ + 20480);
                #pragma unroll
                for (int c = 0; c < 4; ++c) {
                    uint32_t ah[2][4];
                    #pragma unroll
                    for (int mi = 0; mi < 2; ++mi) {
                        const int r = wm*32 + mi*16 + gid;
                        const uint2 u0 = Ah[(r    )*ASTR + c*4 + tig];
                        const uint2 u1 = Ah[(r + 8)*ASTR + c*4 + tig];
                        ah[mi][0] = u0.x; ah[mi][1] = u1.x;
                        ah[mi][2] = u0.y; ah[mi][3] = u1.y;
                    }
                    #pragma unroll
                    for (int ni = 0; ni < 8; ++ni) {
                        const int n = wn*64 + ni*8 + gid;
                        const uint2 ubh = Bh[n*BSTR + c*4 + tig];
                        const uint32_t bhf[2] = {ubh.x, ubh.y};
                        #pragma unroll
                        for (int mi = 0; mi < 2; ++mi)
                            mma16h(acc[mi][ni], ah[mi], bhf);
                    }
                }
            }

            if (has_next) {
                uint2* Ah = (uint2*)(sm + nxt*BUFSZ);
                #pragma unroll
                for (int j = 0; j < 4; ++j) {
                    const int u = sr_[j]*ASTR + sq_[j];
                    Ah[u] = make_uint2(pack2h(pa[j][0].x, pa[j][0].y),
                                       pack2h(pa[j][1].x, pa[j][1].y));
                }
                CP_WAIT0();
            }
            __syncthreads();
            cur = nxt;
        }

        float rs[2][2] = {0.f, 0.f, 0.f, 0.f};
        #pragma unroll
        for (int mi = 0; mi < 2; ++mi) {
            const int r_lo = m0 + wm*32 + mi*16 + gid;
            const float* hlo = (r_lo     >= bsplit) ? h1s : h0s;
            const float* hhi = (r_lo + 8 >= bsplit) ? h1s : h0s;
            #pragma unroll
            for (int ni = 0; ni < 8; ++ni) {
                const int c0 = wn*64 + ni*8 + 2*tig;
                const float w0 = wavs[c0], w1 = wavs[c0+1];
                rs[mi][0] += tanhapx(acc[mi][ni][0] + hlo[c0  ]) * w0
                           + tanhapx(acc[mi][ni][1] + hlo[c0+1]) * w1;
                rs[mi][1] += tanhapx(acc[mi][ni][2] + hhi[c0  ]) * w0
                           + tanhapx(acc[mi][ni][3] + hhi[c0+1]) * w1;
            }
        }
        #pragma unroll
        for (int off = 1; off <= 2; off <<= 1) {
            #pragma unroll
            for (int mi = 0; mi < 2; ++mi) {
                rs[mi][0] += __shfl_xor_sync(0xffffffffu, rs[mi][0], off);
                rs[mi][1] += __shfl_xor_sync(0xffffffffu, rs[mi][1], off);
            }
        }
        if (tig == 0) {
            #pragma unroll
            for (int mi = 0; mi < 2; ++mi) {
                atomicAdd(&zs[wm*32 + mi*16 + gid    ], rs[mi][0]);
                atomicAdd(&zs[wm*32 + mi*16 + gid + 8], rs[mi][1]);
            }
        }
    }
    __syncthreads();
    if (tid < 128) g_z[m0 + tid] = zs[tid] + bav[0];
}

// ---------------------------------------------------------------------------
// K3 fused: per-block s_att + softmax + beta (redundant across y), then
// c_t streaming + gated output. grid (B, 4), 256 thr.
// ---------------------------------------------------------------------------
__global__ void __launch_bounds__(256) k_ct(
    const float* __restrict__ enc, const float* __restrict__ st,
    const float* __restrict__ Was, const float* __restrict__ bas,
    float* __restrict__ out)
{
    __shared__ float zsh[PP];
    __shared__ float alpha_sh[PP];
    __shared__ float red[256];
    __shared__ float4 red4[8][32];
    const int tid = threadIdx.x;
    const int b   = blockIdx.x;
    const int y   = blockIdx.y;

    float sacc = 0.f;
    for (int i = tid; i < AA; i += 256)
        sacc += tanhapx(g_sh[(size_t)b*AA + i]) * Was[i];
    red[tid] = sacc;
    __syncthreads();
    for (int s = 128; s > 0; s >>= 1) {
        if (tid < s) red[tid] += red[tid + s];
        __syncthreads();
    }
    const float sa = red[0] + bas[0];
    __syncthreads();

    if (tid < PP) zsh[tid] = g_z[b*PP + tid];
    __syncthreads();

    red[tid] = (tid < PP) ? zsh[tid] : -1e30f;
    __syncthreads();
    for (int s = 128; s > 0; s >>= 1) {
        if (tid < s) red[tid] = fmaxf(red[tid], red[tid + s]);
        __syncthreads();
    }
    const float m1 = red[0];
    __syncthreads();

    const float e = (tid < PP) ? __expf(zsh[tid] - m1) : 0.f;
    red[tid] = e;
    __syncthreads();
    for (int s = 128; s > 0; s >>= 1) {
        if (tid < s) red[tid] += red[tid + s];
        __syncthreads();
    }
    const float sum1 = red[0];

    if (tid < PP) {
        const float alpha = e / sum1;
        alpha_sh[tid] = alpha;
        if (y == 0) out[BB*DD + b*PP + tid] = alpha;     // alpha_t
    }

    const float m2   = fmaxf(m1, sa);
    const float sum2 = sum1 * __expf(m1 - m2) + __expf(sa - m2);
    const float beta = __expf(sa - m2) / sum2;
    if (y == 0 && tid == 0) out[BB*DD + BB*PP + b] = beta;  // beta_t
    __syncthreads();

    const int q  = tid & 31;
    const int g  = tid >> 5;
    const int d4 = y*128 + q*4;
    const float* eb = enc + (size_t)b*PP*DD + d4;
    float4 a4 = make_float4(0.f, 0.f, 0.f, 0.f);
    #pragma unroll 4
    for (int p = g; p < PP; p += 8) {
        const float4 ev = *(const float4*)(eb + (size_t)p*DD);
        const float al = alpha_sh[p];
        a4.x += ev.x*al; a4.y += ev.y*al; a4.z += ev.z*al; a4.w += ev.w*al;
    }
    red4[g][q] = a4;
    __syncthreads();
    #pragma unroll
    for (int s = 4; s > 0; s >>= 1) {
        if (g < s) {
            float4 o = red4[g + s][q];
            a4.x += o.x; a4.y += o.y; a4.z += o.z; a4.w += o.w;
            red4[g][q] = a4;
        }
        __syncthreads();
    }
    if (g == 0) {
        const float4 s4 = *(const float4*)&st[b*DD + d4];
        float4 o;
        o.x = beta*s4.x + (1.f - beta)*a4.x;
        o.y = beta*s4.y + (1.f - beta)*a4.y;
        o.z = beta*s4.z + (1.f - beta)*a4.z;
        o.w = beta*s4.w + (1.f - beta)*a4.w;
        *(float4*)&out[b*DD + d4] = o;                   // c_hat_t
    }
}

// ---------------------------------------------------------------------------
extern "C" void kernel_launch(void* const* d_in, const int* in_sizes, int n_in,
                              void* d_out, int out_size) {
    const float* enc = (const float*)d_in[0];
    const float* dh  = (const float*)d_in[1];
    const float* st  = (const float*)d_in[2];
    const float* Wv  = (const float*)d_in[3];
    const float* bv  = (const float*)d_in[4];
    const float* Wh  = (const float*)d_in[5];
    const float* bh  = (const float*)d_in[6];
    const float* Ws  = (const float*)d_in[7];
    const float* bs  = (const float*)d_in[8];
    const float* Wav = (const float*)d_in[9];
    const float* bav = (const float*)d_in[10];
    const float* Was = (const float*)d_in[11];
    const float* bas = (const float*)d_in[12];
    float* out = (float*)d_out;

    static int smem_set = 0;
    if (!smem_set) {
        cudaFuncSetAttribute(k_zgemm,
            cudaFuncAttributeMaxDynamicSharedMemorySize, K2_SMEM);
        smem_set = 1;
    }

    k_prepc<<<144, 256>>>(dh, st, Wh, bh, Ws, bs, bv, Wv);
    k_zgemm<<<MM/128, 512, K2_SMEM>>>(enc, Wav, bav);
    k_ct   <<<dim3(BB, 4), 256>>>(enc, st, Was, bas, out);
}